// round 8
// baseline (speedup 1.0000x reference)
#include <cuda_runtime.h>
#include <cstdint>

#define NGRAPH 2048
#define NPG 91
#define DIM 128
#define ORDER 3

// scratch: fv[o,b,:] = feats[last_idx[o,b]] @ Wv[o] + bu[o]  (3 MB)
__device__ float g_fvb[ORDER * NGRAPH * DIM];

// ---------------- kernel 1: fvb ----------------
__global__ void __launch_bounds__(128) fvb_kernel(const float* __restrict__ feats,
                                                  const float* __restrict__ Wv,
                                                  const float* __restrict__ bu,
                                                  const int* __restrict__ last_idx) {
    const int GPB = 16;
    int o  = blockIdx.x / (NGRAPH / GPB);
    int b0 = (blockIdx.x % (NGRAPH / GPB)) * GPB;
    int h  = threadIdx.x;
    __shared__ float xs[GPB][DIM];
    #pragma unroll
    for (int j = 0; j < GPB; j++) {
        int node = last_idx[o * NGRAPH + b0 + j];
        xs[j][h] = feats[node * DIM + h];
    }
    __syncthreads();
    float acc[GPB];
    float bv = bu[o * DIM + h];
    #pragma unroll
    for (int j = 0; j < GPB; j++) acc[j] = bv;
    const float* Wvo = Wv + o * DIM * DIM;
    #pragma unroll 4
    for (int d = 0; d < DIM; d++) {
        float w = Wvo[d * DIM + h];
        #pragma unroll
        for (int j = 0; j < GPB; j++) acc[j] += xs[j][d] * w;
    }
    #pragma unroll
    for (int j = 0; j < GPB; j++)
        g_fvb[(o * NGRAPH + b0 + j) * DIM + h] = acc[j];
}

// ---------------- fused main kernel (512 threads, 16 warps) ----------------
#define MROWS 192
#define LDA 132    // A smem stride: ldmatrix phases hit all 32 banks (4*i mod 32)
#define LDBT 132   // Wu^T smem stride, same property
#define OFF_A   0
#define OFF_WUT (OFF_A + MROWS * LDA)        // 25344
#define OFF_FV  (OFF_WUT + 128 * LDBT)       // 42240
#define OFF_WE  (OFF_FV + 256)               // 42496
#define OFF_ER  (OFF_WE + 128)               // 42624 (4 banks x 192)
#define OFF_AL  (OFF_ER + 768)               // 43392
#define SMEM_FLOATS (OFF_AL + 192)           // 43584 -> 174336 B

__device__ __forceinline__ uint32_t to_tf32(float x) {
    uint32_t u;
    asm("cvt.rna.tf32.f32 %0, %1;" : "=r"(u) : "f"(x));
    return u;
}
__device__ __forceinline__ void mma_tf32(float c[4], const uint32_t a[4],
                                         uint32_t b0, uint32_t b1) {
    asm volatile(
        "mma.sync.aligned.m16n8k8.row.col.f32.tf32.tf32.f32 "
        "{%0,%1,%2,%3}, {%4,%5,%6,%7}, {%8,%9}, {%0,%1,%2,%3};"
        : "+f"(c[0]), "+f"(c[1]), "+f"(c[2]), "+f"(c[3])
        : "r"(a[0]), "r"(a[1]), "r"(a[2]), "r"(a[3]), "r"(b0), "r"(b1));
}
__device__ __forceinline__ void ldsm_x4(uint32_t r[4], uint32_t saddr) {
    asm volatile("ldmatrix.sync.aligned.m8n8.x4.shared.b16 {%0,%1,%2,%3}, [%4];"
                 : "=r"(r[0]), "=r"(r[1]), "=r"(r[2]), "=r"(r[3])
                 : "r"(saddr));
}

__global__ void __launch_bounds__(512, 1) fused_kernel(const float* __restrict__ feats,
                                                       const float* __restrict__ Wu,
                                                       const float* __restrict__ We,
                                                       float* __restrict__ out) {
    extern __shared__ float sm[];
    float* sA   = sm + OFF_A;     // tf32-rounded feats, 192 rows x 128 (LDA stride)
    float* sWuT = sm + OFF_WUT;   // tf32-rounded Wu[o]^T: [h][d] (LDBT stride)
    float* sFV  = sm + OFF_FV;
    float* sWe  = sm + OFF_WE;
    float* sER  = sm + OFF_ER;
    float* sAL  = sm + OFF_AL;

    const int tid   = threadIdx.x;
    const int g0    = blockIdx.x * 2;       // 2 graphs per CTA
    const int lane  = tid & 31;
    const int wid   = tid >> 5;
    const int warpM = wid >> 2;             // 0..3 -> 48 rows each
    const int warpN = wid & 3;              // 0..3 -> 32 cols each
    const int gid   = lane >> 2;
    const int tig   = lane & 3;

    // stage feats (pre-rounded to tf32): 182 rows + 10 zero pad rows
    {
        const float4* f4 = (const float4*)(feats + g0 * NPG * DIM);
        for (int i = tid; i < 182 * 32; i += 512) {
            int r = i >> 5, c = i & 31;
            float4 v = f4[i];
            uint32_t* d = (uint32_t*)(sA + r * LDA + c * 4);
            d[0] = to_tf32(v.x); d[1] = to_tf32(v.y);
            d[2] = to_tf32(v.z); d[3] = to_tf32(v.w);
        }
        if (tid < 10 * 32) {
            int r = 182 + (tid >> 5), c = tid & 31;
            *(float4*)(sA + r * LDA + c * 4) = make_float4(0.f, 0.f, 0.f, 0.f);
        }
    }

    // ldmatrix base addresses (byte offsets into shared space)
    uint32_t aBase[3];
    #pragma unroll
    for (int mt = 0; mt < 3; mt++) {
        const float* p = sA + (warpM * 48 + mt * 16 + (lane & 15)) * LDA
                       + ((lane >> 4) << 2);
        aBase[mt] = (uint32_t)__cvta_generic_to_shared(p);
    }
    uint32_t bBase[2];
    #pragma unroll
    for (int p2 = 0; p2 < 2; p2++) {
        const float* p = sWuT
            + (warpN * 32 + p2 * 16 + ((lane >> 4) << 3) + (lane & 7)) * LDBT
            + (((lane >> 3) & 1) << 2);
        bBase[p2] = (uint32_t)__cvta_generic_to_shared(p);
    }

    for (int o = 0; o < ORDER; o++) {
        if (o > 0) __syncthreads();
        // stage Wu[o]^T (tf32), fv+bu for both graphs, We[o]
        {
            const float* wo = Wu + o * DIM * DIM;
            for (int i = tid; i < DIM * DIM; i += 512) {
                int k = i >> 7, n = i & 127;              // coalesced global read
                sWuT[n * LDBT + k] = __uint_as_float(to_tf32(wo[i]));
            }
            if (tid < 256) {
                int g = tid >> 7, h = tid & 127;
                sFV[tid] = g_fvb[(o * NGRAPH + g0 + g) * DIM + h];
            }
            if (tid >= 256 && tid < 384) sWe[tid - 256] = We[o * DIM + (tid - 256)];
        }
        __syncthreads();

        float acc[3][4][4];
        #pragma unroll
        for (int mt = 0; mt < 3; mt++)
            #pragma unroll
            for (int nt = 0; nt < 4; nt++) {
                acc[mt][nt][0] = 0.f; acc[mt][nt][1] = 0.f;
                acc[mt][nt][2] = 0.f; acc[mt][nt][3] = 0.f;
            }

        #pragma unroll
        for (int ks = 0; ks < 16; ks++) {
            const uint32_t kb = (uint32_t)(ks * 8 * 4);   // byte offset of k0
            uint32_t afr[3][4];
            #pragma unroll
            for (int mt = 0; mt < 3; mt++) ldsm_x4(afr[mt], aBase[mt] + kb);
            uint32_t bfr[2][4];   // bfr[p] = {b(2p)0, b(2p)1, b(2p+1)0, b(2p+1)1}
            #pragma unroll
            for (int p2 = 0; p2 < 2; p2++) ldsm_x4(bfr[p2], bBase[p2] + kb);
            #pragma unroll
            for (int mt = 0; mt < 3; mt++) {
                #pragma unroll
                for (int p2 = 0; p2 < 2; p2++) {
                    mma_tf32(acc[mt][2 * p2],     afr[mt], bfr[p2][0], bfr[p2][1]);
                    mma_tf32(acc[mt][2 * p2 + 1], afr[mt], bfr[p2][2], bfr[p2][3]);
                }
            }
        }

        // epilogue: e-row partials = sum_h sigmoid(acc + fv) * We[h]
        float ep[3][2];
        #pragma unroll
        for (int mt = 0; mt < 3; mt++) { ep[mt][0] = 0.f; ep[mt][1] = 0.f; }
        #pragma unroll
        for (int mt = 0; mt < 3; mt++) {
            int m0 = warpM * 48 + mt * 16 + gid;
            int m1 = m0 + 8;
            int fo0 = (m0 < NPG ? 0 : DIM);
            int fo1 = (m1 < NPG ? 0 : DIM);
            #pragma unroll
            for (int nt = 0; nt < 4; nt++) {
                int h = warpN * 32 + nt * 8 + tig * 2;
                float we0 = sWe[h], we1 = sWe[h + 1];
                if (m0 < 182) {
                    float v0 = acc[mt][nt][0] + sFV[fo0 + h];
                    float v1 = acc[mt][nt][1] + sFV[fo0 + h + 1];
                    ep[mt][0] += __fdividef(we0, 1.f + __expf(-v0))
                               + __fdividef(we1, 1.f + __expf(-v1));
                }
                if (m1 < 182) {
                    float v2 = acc[mt][nt][2] + sFV[fo1 + h];
                    float v3 = acc[mt][nt][3] + sFV[fo1 + h + 1];
                    ep[mt][1] += __fdividef(we0, 1.f + __expf(-v2))
                               + __fdividef(we1, 1.f + __expf(-v3));
                }
            }
        }
        #pragma unroll
        for (int mt = 0; mt < 3; mt++)
            #pragma unroll
            for (int q = 0; q < 2; q++) {
                float v = ep[mt][q];
                v += __shfl_xor_sync(0xffffffffu, v, 1);
                v += __shfl_xor_sync(0xffffffffu, v, 2);
                if (tig == 0)
                    sER[warpN * 192 + warpM * 48 + mt * 16 + gid + q * 8] = v;
            }
        __syncthreads();

        // per-graph softmax over 91 nodes (warp 0 -> graph 0, warp 1 -> graph 1)
        if (wid < 2) {
            int gbase = wid * NPG;
            float ev[3];
            #pragma unroll
            for (int j = 0; j < 3; j++) {
                int r = lane + 32 * j;
                ev[j] = (r < NPG) ? (sER[gbase + r] + sER[192 + gbase + r] +
                                     sER[384 + gbase + r] + sER[576 + gbase + r])
                                  : -1e30f;
            }
            float mx = fmaxf(ev[0], fmaxf(ev[1], ev[2]));
            #pragma unroll
            for (int s = 16; s; s >>= 1)
                mx = fmaxf(mx, __shfl_xor_sync(0xffffffffu, mx, s));
            float sum = 0.f;
            #pragma unroll
            for (int j = 0; j < 3; j++) {
                ev[j] = (lane + 32 * j < NPG) ? __expf(ev[j] - mx) : 0.f;
                sum += ev[j];
            }
            #pragma unroll
            for (int s = 16; s; s >>= 1)
                sum += __shfl_xor_sync(0xffffffffu, sum, s);
            float inv = 1.f / sum;
            #pragma unroll
            for (int j = 0; j < 3; j++) {
                int r = lane + 32 * j;
                if (r < NPG) sAL[gbase + r] = ev[j] * inv;
            }
        }
        __syncthreads();

        // rst[b,o,:] = sum_m alpha[m] * feats[m,:]  (split rows across 2 halves)
        {
            int g    = tid >> 8;          // 0..1 graph
            int part = (tid >> 7) & 1;    // 0..1 row half
            int h    = tid & 127;
            int r0i  = part * 46;
            int cnt  = part ? 45 : 46;
            const float* aBaseF  = sA + (g * NPG + r0i) * LDA + h;
            const float* alBase = sAL + g * NPG + r0i;
            float r0 = 0.f;
            #pragma unroll 5
            for (int r = 0; r < cnt; r++) r0 += alBase[r] * aBaseF[r * LDA];
            if (part) sER[g * 128 + h] = r0;   // reuse sER as partial buffer
            __syncthreads();
            if (!part)
                out[((g0 + g) * ORDER + o) * DIM + h] = r0 + sER[g * 128 + h];
        }
    }
}

extern "C" void kernel_launch(void* const* d_in, const int* in_sizes, int n_in,
                              void* d_out, int out_size) {
    const float* feats    = (const float*)d_in[0];
    const float* Wu       = (const float*)d_in[1];
    const float* bu       = (const float*)d_in[2];
    const float* Wv       = (const float*)d_in[3];
    const float* We       = (const float*)d_in[4];
    const int*   last_idx = (const int*)d_in[6];
    float* out = (float*)d_out;

    fvb_kernel<<<ORDER * (NGRAPH / 16), 128>>>(feats, Wv, bu, last_idx);

    cudaFuncSetAttribute(fused_kernel, cudaFuncAttributeMaxDynamicSharedMemorySize,
                         SMEM_FLOATS * (int)sizeof(float));
    fused_kernel<<<NGRAPH / 2, 512, SMEM_FLOATS * sizeof(float)>>>(feats, Wu, We, out);
}

// round 10
// speedup vs baseline: 1.3584x; 1.3584x over previous
#include <cuda_runtime.h>
#include <cuda_fp16.h>
#include <cstdint>

#define NGRAPH 2048
#define NPG 91
#define DIM 128
#define ORDER 3

// scratch
__device__ float    g_fvb[ORDER * NGRAPH * DIM];     // fv + bu (3 MB)
__device__ uint32_t g_wuth[ORDER * 128 * 68];        // Wu^T fp16, padded (stride 136 halves)

// ---------------- kernel 1: fvb ----------------
__global__ void __launch_bounds__(128) fvb_kernel(const float* __restrict__ feats,
                                                  const float* __restrict__ Wv,
                                                  const float* __restrict__ bu,
                                                  const int* __restrict__ last_idx) {
    const int GPB = 16;
    int o  = blockIdx.x / (NGRAPH / GPB);
    int b0 = (blockIdx.x % (NGRAPH / GPB)) * GPB;
    int h  = threadIdx.x;
    __shared__ float xs[GPB][DIM];
    #pragma unroll
    for (int j = 0; j < GPB; j++) {
        int node = last_idx[o * NGRAPH + b0 + j];
        xs[j][h] = feats[node * DIM + h];
    }
    __syncthreads();
    float acc[GPB];
    float bv = bu[o * DIM + h];
    #pragma unroll
    for (int j = 0; j < GPB; j++) acc[j] = bv;
    const float* Wvo = Wv + o * DIM * DIM;
    #pragma unroll 4
    for (int d = 0; d < DIM; d++) {
        float w = Wvo[d * DIM + h];
        #pragma unroll
        for (int j = 0; j < GPB; j++) acc[j] += xs[j][d] * w;
    }
    #pragma unroll
    for (int j = 0; j < GPB; j++)
        g_fvb[(o * NGRAPH + b0 + j) * DIM + h] = acc[j];
}

// ---------------- kernel 2: prep Wu^T fp16 padded image ----------------
// image[o][n*68 + d2] = half2(Wu[o][2*d2][n], Wu[o][2*d2+1][n])
__global__ void __launch_bounds__(512) prep_wuth(const float* __restrict__ Wu) {
    int o = blockIdx.x;
    const float* w = Wu + o * DIM * DIM;
    for (int i = threadIdx.x; i < 64 * 128; i += 512) {
        int d2 = i & 63, n = i >> 6;
        float a = w[(2 * d2) * DIM + n];
        float b = w[(2 * d2 + 1) * DIM + n];
        __half2 p = __floats2half2_rn(a, b);
        g_wuth[o * 128 * 68 + n * 68 + d2] = *(uint32_t*)&p;
    }
}

// ---------------- fused main kernel (512 threads, 16 warps) ----------------
// A: 192 rows x 128 halves, row stride 136 halves (272B) -> ldmatrix conflict-free
// WuT: 128 rows x 128 halves, stride 136
#define LDAH 136
#define OFF_A   0                         // 192*136 halves = 52224 B
#define OFF_WUT 52224                     // 128*136 halves = 34816 B
#define OFF_FV  87040                     // 256 floats
#define OFF_WE  88064                     // 128 floats
#define OFF_ER  88576                     // 768 floats
#define OFF_AL  91648                     // 192 floats
#define SMEM_BYTES 92416

__device__ __forceinline__ void ldsm_x4(uint32_t r[4], uint32_t saddr) {
    asm volatile("ldmatrix.sync.aligned.m8n8.x4.shared.b16 {%0,%1,%2,%3}, [%4];"
                 : "=r"(r[0]), "=r"(r[1]), "=r"(r[2]), "=r"(r[3])
                 : "r"(saddr));
}
__device__ __forceinline__ void mma_f16(float c[4], const uint32_t a[4],
                                        uint32_t b0, uint32_t b1) {
    asm volatile(
        "mma.sync.aligned.m16n8k16.row.col.f32.f16.f16.f32 "
        "{%0,%1,%2,%3}, {%4,%5,%6,%7}, {%8,%9}, {%0,%1,%2,%3};"
        : "+f"(c[0]), "+f"(c[1]), "+f"(c[2]), "+f"(c[3])
        : "r"(a[0]), "r"(a[1]), "r"(a[2]), "r"(a[3]), "r"(b0), "r"(b1));
}

__global__ void __launch_bounds__(512, 1) fused_kernel(const float* __restrict__ feats,
                                                       const float* __restrict__ We,
                                                       float* __restrict__ out) {
    extern __shared__ char smc[];
    uint2*  sA2  = (uint2*)(smc + OFF_A);          // 4 halves per uint2
    float4* sWuT4 = (float4*)(smc + OFF_WUT);
    float*  sFV  = (float*)(smc + OFF_FV);
    float*  sWe  = (float*)(smc + OFF_WE);
    float*  sER  = (float*)(smc + OFF_ER);
    float*  sAL  = (float*)(smc + OFF_AL);
    const __half* sAh = (const __half*)(smc + OFF_A);

    const int tid   = threadIdx.x;
    const int g0    = blockIdx.x * 2;     // 2 graphs per CTA
    const int lane  = tid & 31;
    const int wid   = tid >> 5;
    const int warpM = wid >> 2;           // 0..3 -> 48 rows
    const int warpN = wid & 3;            // 0..3 -> 32 cols
    const int gid   = lane >> 2;
    const int tig   = lane & 3;

    // stage feats as fp16: 182 rows + 10 zero pad rows
    {
        const float4* f4 = (const float4*)(feats + (size_t)g0 * NPG * DIM);
        for (int i = tid; i < 182 * 32; i += 512) {
            int r = i >> 5, c = i & 31;   // floats 4c..4c+3 of row r
            float4 v = f4[i];
            __half2 p0 = __floats2half2_rn(v.x, v.y);
            __half2 p1 = __floats2half2_rn(v.z, v.w);
            sA2[r * 34 + c] = make_uint2(*(uint32_t*)&p0, *(uint32_t*)&p1);
        }
        if (tid < 320) {
            int r = 182 + (tid >> 5), c = tid & 31;
            sA2[r * 34 + c] = make_uint2(0u, 0u);
        }
    }

    // ldmatrix base addresses
    uint32_t aBase[3];
    #pragma unroll
    for (int mt = 0; mt < 3; mt++) {
        const __half* p = sAh + (warpM * 48 + mt * 16 + (lane & 15)) * LDAH
                        + ((lane >> 4) << 3);
        aBase[mt] = (uint32_t)__cvta_generic_to_shared(p);
    }
    uint32_t bBase[2];
    #pragma unroll
    for (int p2 = 0; p2 < 2; p2++) {
        const __half* p = (const __half*)(smc + OFF_WUT)
            + (warpN * 32 + p2 * 16 + ((lane >> 4) << 3) + (lane & 7)) * LDAH
            + (((lane >> 3) & 1) << 3);
        bBase[p2] = (uint32_t)__cvta_generic_to_shared(p);
    }

    for (int o = 0; o < ORDER; o++) {
        if (o > 0) __syncthreads();
        // stage Wu^T image (pure copy), fv+bu, We
        {
            const float4* src = (const float4*)(g_wuth + o * 128 * 68);
            for (int i = tid; i < 128 * 17; i += 512)   // 2176 float4
                sWuT4[i] = src[i];
            if (tid < 256) {
                int g = tid >> 7, h = tid & 127;
                sFV[tid] = g_fvb[(o * NGRAPH + g0 + g) * DIM + h];
            }
            if (tid >= 256 && tid < 384) sWe[tid - 256] = We[o * DIM + (tid - 256)];
        }
        __syncthreads();

        float acc[3][4][4];
        #pragma unroll
        for (int mt = 0; mt < 3; mt++)
            #pragma unroll
            for (int nt = 0; nt < 4; nt++) {
                acc[mt][nt][0] = 0.f; acc[mt][nt][1] = 0.f;
                acc[mt][nt][2] = 0.f; acc[mt][nt][3] = 0.f;
            }

        #pragma unroll
        for (int ks = 0; ks < 8; ks++) {
            const uint32_t kb = (uint32_t)(ks * 32);   // 16 halves per step
            uint32_t afr[3][4];
            #pragma unroll
            for (int mt = 0; mt < 3; mt++) ldsm_x4(afr[mt], aBase[mt] + kb);
            uint32_t bfr[2][4];  // {b0_t(2p), b1_t(2p), b0_t(2p+1), b1_t(2p+1)}
            #pragma unroll
            for (int p2 = 0; p2 < 2; p2++) ldsm_x4(bfr[p2], bBase[p2] + kb);
            #pragma unroll
            for (int mt = 0; mt < 3; mt++) {
                #pragma unroll
                for (int p2 = 0; p2 < 2; p2++) {
                    mma_f16(acc[mt][2 * p2],     afr[mt], bfr[p2][0], bfr[p2][1]);
                    mma_f16(acc[mt][2 * p2 + 1], afr[mt], bfr[p2][2], bfr[p2][3]);
                }
            }
        }

        // epilogue: e-row partials = sum_h sigmoid(acc + fv) * We[h]
        float ep[3][2];
        #pragma unroll
        for (int mt = 0; mt < 3; mt++) { ep[mt][0] = 0.f; ep[mt][1] = 0.f; }
        #pragma unroll
        for (int mt = 0; mt < 3; mt++) {
            int m0 = warpM * 48 + mt * 16 + gid;
            int m1 = m0 + 8;
            int fo0 = (m0 < NPG ? 0 : DIM);
            int fo1 = (m1 < NPG ? 0 : DIM);
            #pragma unroll
            for (int nt = 0; nt < 4; nt++) {
                int h = warpN * 32 + nt * 8 + tig * 2;
                float we0 = sWe[h], we1 = sWe[h + 1];
                if (m0 < 182) {
                    float x0 = 0.5f * (acc[mt][nt][0] + sFV[fo0 + h]);
                    float x1 = 0.5f * (acc[mt][nt][1] + sFV[fo0 + h + 1]);
                    float t0, t1;
                    asm("tanh.approx.f32 %0, %1;" : "=f"(t0) : "f"(x0));
                    asm("tanh.approx.f32 %0, %1;" : "=f"(t1) : "f"(x1));
                    ep[mt][0] += we0 * (0.5f * t0 + 0.5f) + we1 * (0.5f * t1 + 0.5f);
                }
                if (m1 < 182) {
                    float x2 = 0.5f * (acc[mt][nt][2] + sFV[fo1 + h]);
                    float x3 = 0.5f * (acc[mt][nt][3] + sFV[fo1 + h + 1]);
                    float t2, t3;
                    asm("tanh.approx.f32 %0, %1;" : "=f"(t2) : "f"(x2));
                    asm("tanh.approx.f32 %0, %1;" : "=f"(t3) : "f"(x3));
                    ep[mt][1] += we0 * (0.5f * t2 + 0.5f) + we1 * (0.5f * t3 + 0.5f);
                }
            }
        }
        #pragma unroll
        for (int mt = 0; mt < 3; mt++)
            #pragma unroll
            for (int q = 0; q < 2; q++) {
                float v = ep[mt][q];
                v += __shfl_xor_sync(0xffffffffu, v, 1);
                v += __shfl_xor_sync(0xffffffffu, v, 2);
                if (tig == 0)
                    sER[warpN * 192 + warpM * 48 + mt * 16 + gid + q * 8] = v;
            }
        __syncthreads();

        // per-graph softmax over 91 nodes
        if (wid < 2) {
            int gbase = wid * NPG;
            float ev[3];
            #pragma unroll
            for (int j = 0; j < 3; j++) {
                int r = lane + 32 * j;
                ev[j] = (r < NPG) ? (sER[gbase + r] + sER[192 + gbase + r] +
                                     sER[384 + gbase + r] + sER[576 + gbase + r])
                                  : -1e30f;
            }
            float mx = fmaxf(ev[0], fmaxf(ev[1], ev[2]));
            #pragma unroll
            for (int s = 16; s; s >>= 1)
                mx = fmaxf(mx, __shfl_xor_sync(0xffffffffu, mx, s));
            float sum = 0.f;
            #pragma unroll
            for (int j = 0; j < 3; j++) {
                ev[j] = (lane + 32 * j < NPG) ? __expf(ev[j] - mx) : 0.f;
                sum += ev[j];
            }
            #pragma unroll
            for (int s = 16; s; s >>= 1)
                sum += __shfl_xor_sync(0xffffffffu, sum, s);
            float inv = 1.f / sum;
            #pragma unroll
            for (int j = 0; j < 3; j++) {
                int r = lane + 32 * j;
                if (r < NPG) sAL[gbase + r] = ev[j] * inv;
            }
        }
        __syncthreads();

        // rst[b,o,:] = sum_m alpha[m] * feats_h[m,:]
        {
            int g    = tid >> 8;
            int part = (tid >> 7) & 1;
            int h    = tid & 127;
            int r0i  = part * 46;
            int cnt  = part ? 45 : 46;
            const __half* aB    = sAh + (g * NPG + r0i) * LDAH + h;
            const float*  alB   = sAL + g * NPG + r0i;
            float r0 = 0.f;
            #pragma unroll 5
            for (int r = 0; r < cnt; r++)
                r0 += alB[r] * __half2float(aB[r * LDAH]);
            if (part) sER[g * 128 + h] = r0;
            __syncthreads();
            if (!part)
                out[((g0 + g) * ORDER + o) * DIM + h] = r0 + sER[g * 128 + h];
        }
    }
}

extern "C" void kernel_launch(void* const* d_in, const int* in_sizes, int n_in,
                              void* d_out, int out_size) {
    const float* feats    = (const float*)d_in[0];
    const float* Wu       = (const float*)d_in[1];
    const float* bu       = (const float*)d_in[2];
    const float* Wv       = (const float*)d_in[3];
    const float* We       = (const float*)d_in[4];
    const int*   last_idx = (const int*)d_in[6];
    float* out = (float*)d_out;

    fvb_kernel<<<ORDER * (NGRAPH / 16), 128>>>(feats, Wv, bu, last_idx);
    prep_wuth<<<ORDER, 512>>>(Wu);

    cudaFuncSetAttribute(fused_kernel, cudaFuncAttributeMaxDynamicSharedMemorySize,
                         SMEM_BYTES);
    fused_kernel<<<NGRAPH / 2, 512, SMEM_BYTES>>>(feats, We, out);
}

// round 11
// speedup vs baseline: 1.4838x; 1.0923x over previous
#include <cuda_runtime.h>
#include <cuda_fp16.h>
#include <cstdint>

#define NGRAPH 2048
#define NPG 91
#define DIM 128
#define ORDER 3

// scratch
__device__ float    g_fvb[ORDER * NGRAPH * DIM];     // fv + bu (3 MB)
__device__ uint32_t g_wuth[ORDER * 128 * 68];        // Wu^T fp16, padded (stride 136 halves)

// ---------------- kernel 1: fvb (blocks 0..767) + prep Wu^T (blocks 768..770)
__global__ void __launch_bounds__(128) prep_kernel(const float* __restrict__ feats,
                                                   const float* __restrict__ Wu,
                                                   const float* __restrict__ Wv,
                                                   const float* __restrict__ bu,
                                                   const int* __restrict__ last_idx) {
    if (blockIdx.x >= 768) {
        // prep Wu^T fp16 padded image: image[o][n*68+d2] = half2(Wu[2d2][n], Wu[2d2+1][n])
        int o = blockIdx.x - 768;
        const float* w = Wu + o * DIM * DIM;
        for (int i = threadIdx.x; i < 64 * 128; i += 128) {
            int d2 = i & 63, n = i >> 6;
            float a = w[(2 * d2) * DIM + n];
            float b = w[(2 * d2 + 1) * DIM + n];
            __half2 p = __floats2half2_rn(a, b);
            g_wuth[o * 128 * 68 + n * 68 + d2] = *(uint32_t*)&p;
        }
        return;
    }
    const int GPB = 8;
    int o  = blockIdx.x / (NGRAPH / GPB);
    int b0 = (blockIdx.x % (NGRAPH / GPB)) * GPB;
    int h  = threadIdx.x;
    __shared__ float xs[GPB][DIM];
    #pragma unroll
    for (int j = 0; j < GPB; j++) {
        int node = last_idx[o * NGRAPH + b0 + j];
        xs[j][h] = feats[node * DIM + h];
    }
    __syncthreads();
    float acc[GPB];
    float bv = bu[o * DIM + h];
    #pragma unroll
    for (int j = 0; j < GPB; j++) acc[j] = bv;
    const float* Wvo = Wv + o * DIM * DIM;
    #pragma unroll 8
    for (int d = 0; d < DIM; d++) {
        float w = Wvo[d * DIM + h];
        #pragma unroll
        for (int j = 0; j < GPB; j++) acc[j] += xs[j][d] * w;
    }
    #pragma unroll
    for (int j = 0; j < GPB; j++)
        g_fvb[(o * NGRAPH + b0 + j) * DIM + h] = acc[j];
}

// ---------------- fused main kernel (1024 threads, 32 warps) ----------------
// A: 192 rows x 128 halves, row stride 136 halves (272B) -> ldmatrix conflict-free
// WuT: 128 rows x 128 halves, stride 136
#define LDAH 136
#define OFF_A   0                         // 52224 B
#define OFF_WUT 52224                     // 34816 B
#define OFF_FV  87040                     // 256 floats
#define OFF_WE  88064                     // 128 floats
#define OFF_ER  88576                     // 1536 floats (8 banks x 192)
#define OFF_AL  94720                     // 192 floats
#define SMEM_BYTES 95488

__device__ __forceinline__ void ldsm_x4(uint32_t r[4], uint32_t saddr) {
    asm volatile("ldmatrix.sync.aligned.m8n8.x4.shared.b16 {%0,%1,%2,%3}, [%4];"
                 : "=r"(r[0]), "=r"(r[1]), "=r"(r[2]), "=r"(r[3])
                 : "r"(saddr));
}
__device__ __forceinline__ void mma_f16(float c[4], const uint32_t a[4],
                                        uint32_t b0, uint32_t b1) {
    asm volatile(
        "mma.sync.aligned.m16n8k16.row.col.f32.f16.f16.f32 "
        "{%0,%1,%2,%3}, {%4,%5,%6,%7}, {%8,%9}, {%0,%1,%2,%3};"
        : "+f"(c[0]), "+f"(c[1]), "+f"(c[2]), "+f"(c[3])
        : "r"(a[0]), "r"(a[1]), "r"(a[2]), "r"(a[3]), "r"(b0), "r"(b1));
}

__global__ void __launch_bounds__(1024, 1) fused_kernel(const float* __restrict__ feats,
                                                        const float* __restrict__ We,
                                                        float* __restrict__ out) {
    extern __shared__ char smc[];
    uint2*  sA2   = (uint2*)(smc + OFF_A);
    float4* sWuT4 = (float4*)(smc + OFF_WUT);
    float*  sFV   = (float*)(smc + OFF_FV);
    float*  sWe   = (float*)(smc + OFF_WE);
    float*  sER   = (float*)(smc + OFF_ER);
    float*  sAL   = (float*)(smc + OFF_AL);
    const __half* sAh = (const __half*)(smc + OFF_A);

    const int tid   = threadIdx.x;
    const int g0    = blockIdx.x * 2;     // 2 graphs per CTA
    const int lane  = tid & 31;
    const int wid   = tid >> 5;
    const int warpM = wid >> 3;           // 0..3 -> 48 rows
    const int warpN = wid & 7;            // 0..7 -> 16 cols
    const int gid   = lane >> 2;
    const int tig   = lane & 3;

    // stage feats as fp16: 182 rows + 10 zero pad rows
    {
        const float4* f4 = (const float4*)(feats + (size_t)g0 * NPG * DIM);
        for (int i = tid; i < 182 * 32; i += 1024) {
            int r = i >> 5, c = i & 31;
            float4 v = f4[i];
            __half2 p0 = __floats2half2_rn(v.x, v.y);
            __half2 p1 = __floats2half2_rn(v.z, v.w);
            sA2[r * 34 + c] = make_uint2(*(uint32_t*)&p0, *(uint32_t*)&p1);
        }
        if (tid < 320) {
            int r = 182 + (tid >> 5), c = tid & 31;
            sA2[r * 34 + c] = make_uint2(0u, 0u);
        }
    }

    // ldmatrix base addresses
    uint32_t aBase[3];
    #pragma unroll
    for (int mt = 0; mt < 3; mt++) {
        const __half* p = sAh + (warpM * 48 + mt * 16 + (lane & 15)) * LDAH
                        + ((lane >> 4) << 3);
        aBase[mt] = (uint32_t)__cvta_generic_to_shared(p);
    }
    uint32_t bBase;
    {
        const __half* p = (const __half*)(smc + OFF_WUT)
            + (warpN * 16 + ((lane >> 4) << 3) + (lane & 7)) * LDAH
            + (((lane >> 3) & 1) << 3);
        bBase = (uint32_t)__cvta_generic_to_shared(p);
    }

    for (int o = 0; o < ORDER; o++) {
        if (o > 0) __syncthreads();
        // stage Wu^T image (pure copy), fv+bu, We
        {
            const float4* src = (const float4*)(g_wuth + o * 128 * 68);
            for (int i = tid; i < 128 * 17; i += 1024)
                sWuT4[i] = src[i];
            if (tid < 256) {
                int g = tid >> 7, h = tid & 127;
                sFV[tid] = g_fvb[(o * NGRAPH + g0 + g) * DIM + h];
            }
            if (tid >= 256 && tid < 384) sWe[tid - 256] = We[o * DIM + (tid - 256)];
        }
        __syncthreads();

        float acc[3][2][4];
        #pragma unroll
        for (int mt = 0; mt < 3; mt++)
            #pragma unroll
            for (int nt = 0; nt < 2; nt++) {
                acc[mt][nt][0] = 0.f; acc[mt][nt][1] = 0.f;
                acc[mt][nt][2] = 0.f; acc[mt][nt][3] = 0.f;
            }

        #pragma unroll
        for (int ks = 0; ks < 8; ks++) {
            const uint32_t kb = (uint32_t)(ks * 32);   // 16 halves per step
            uint32_t afr[3][4];
            #pragma unroll
            for (int mt = 0; mt < 3; mt++) ldsm_x4(afr[mt], aBase[mt] + kb);
            uint32_t bfr[4];  // {nt0.b0, nt0.b1, nt1.b0, nt1.b1}
            ldsm_x4(bfr, bBase + kb);
            #pragma unroll
            for (int mt = 0; mt < 3; mt++) {
                mma_f16(acc[mt][0], afr[mt], bfr[0], bfr[1]);
                mma_f16(acc[mt][1], afr[mt], bfr[2], bfr[3]);
            }
        }

        // epilogue: e-row partials = sum_h sigmoid(acc + fv) * We[h]
        float ep[3][2];
        #pragma unroll
        for (int mt = 0; mt < 3; mt++) { ep[mt][0] = 0.f; ep[mt][1] = 0.f; }
        #pragma unroll
        for (int mt = 0; mt < 3; mt++) {
            int m0 = warpM * 48 + mt * 16 + gid;
            int m1 = m0 + 8;
            int fo0 = (m0 < NPG ? 0 : DIM);
            int fo1 = (m1 < NPG ? 0 : DIM);
            #pragma unroll
            for (int nt = 0; nt < 2; nt++) {
                int h = warpN * 16 + nt * 8 + tig * 2;
                float we0 = sWe[h], we1 = sWe[h + 1];
                if (m0 < 182) {
                    float x0 = 0.5f * (acc[mt][nt][0] + sFV[fo0 + h]);
                    float x1 = 0.5f * (acc[mt][nt][1] + sFV[fo0 + h + 1]);
                    float t0, t1;
                    asm("tanh.approx.f32 %0, %1;" : "=f"(t0) : "f"(x0));
                    asm("tanh.approx.f32 %0, %1;" : "=f"(t1) : "f"(x1));
                    ep[mt][0] += we0 * (0.5f * t0 + 0.5f) + we1 * (0.5f * t1 + 0.5f);
                }
                if (m1 < 182) {
                    float x2 = 0.5f * (acc[mt][nt][2] + sFV[fo1 + h]);
                    float x3 = 0.5f * (acc[mt][nt][3] + sFV[fo1 + h + 1]);
                    float t2, t3;
                    asm("tanh.approx.f32 %0, %1;" : "=f"(t2) : "f"(x2));
                    asm("tanh.approx.f32 %0, %1;" : "=f"(t3) : "f"(x3));
                    ep[mt][1] += we0 * (0.5f * t2 + 0.5f) + we1 * (0.5f * t3 + 0.5f);
                }
            }
        }
        #pragma unroll
        for (int mt = 0; mt < 3; mt++)
            #pragma unroll
            for (int q = 0; q < 2; q++) {
                float v = ep[mt][q];
                v += __shfl_xor_sync(0xffffffffu, v, 1);
                v += __shfl_xor_sync(0xffffffffu, v, 2);
                if (tig == 0)
                    sER[warpN * 192 + warpM * 48 + mt * 16 + gid + q * 8] = v;
            }
        __syncthreads();

        // per-graph softmax over 91 nodes (warps 0,1)
        if (wid < 2) {
            int gbase = wid * NPG;
            float ev[3];
            #pragma unroll
            for (int j = 0; j < 3; j++) {
                int r = lane + 32 * j;
                if (r < NPG) {
                    float s = 0.f;
                    #pragma unroll
                    for (int bk = 0; bk < 8; bk++) s += sER[bk * 192 + gbase + r];
                    ev[j] = s;
                } else ev[j] = -1e30f;
            }
            float mx = fmaxf(ev[0], fmaxf(ev[1], ev[2]));
            #pragma unroll
            for (int s = 16; s; s >>= 1)
                mx = fmaxf(mx, __shfl_xor_sync(0xffffffffu, mx, s));
            float sum = 0.f;
            #pragma unroll
            for (int j = 0; j < 3; j++) {
                ev[j] = (lane + 32 * j < NPG) ? __expf(ev[j] - mx) : 0.f;
                sum += ev[j];
            }
            #pragma unroll
            for (int s = 16; s; s >>= 1)
                sum += __shfl_xor_sync(0xffffffffu, sum, s);
            float inv = 1.f / sum;
            #pragma unroll
            for (int j = 0; j < 3; j++) {
                int r = lane + 32 * j;
                if (r < NPG) sAL[gbase + r] = ev[j] * inv;
            }
        }
        __syncthreads();

        // rst[b,o,:] = sum_m alpha[m] * feats_h[m,:]  (4 row-parts per graph)
        {
            int g    = tid >> 9;          // graph 0/1
            int part = (tid >> 7) & 3;    // row quarter
            int h    = tid & 127;
            int r0i  = part * 23;
            int cnt  = (part == 3) ? 22 : 23;
            const __half* aB  = sAh + (g * NPG + r0i) * LDAH + h;
            const float*  alB = sAL + g * NPG + r0i;
            float r0 = 0.f;
            #pragma unroll 23
            for (int r = 0; r < cnt; r++)
                r0 += alB[r] * __half2float(aB[r * LDAH]);
            if (part) sER[(g * 3 + part - 1) * 128 + h] = r0;
            __syncthreads();
            if (!part)
                out[((g0 + g) * ORDER + o) * DIM + h] =
                    r0 + sER[(g * 3 + 0) * 128 + h]
                       + sER[(g * 3 + 1) * 128 + h]
                       + sER[(g * 3 + 2) * 128 + h];
        }
    }
}

extern "C" void kernel_launch(void* const* d_in, const int* in_sizes, int n_in,
                              void* d_out, int out_size) {
    const float* feats    = (const float*)d_in[0];
    const float* Wu       = (const float*)d_in[1];
    const float* bu       = (const float*)d_in[2];
    const float* Wv       = (const float*)d_in[3];
    const float* We       = (const float*)d_in[4];
    const int*   last_idx = (const int*)d_in[6];
    float* out = (float*)d_out;

    prep_kernel<<<768 + ORDER, 128>>>(feats, Wu, Wv, bu, last_idx);

    cudaFuncSetAttribute(fused_kernel, cudaFuncAttributeMaxDynamicSharedMemorySize,
                         SMEM_BYTES);
    fused_kernel<<<NGRAPH / 2, 1024, SMEM_BYTES>>>(feats, We, out);
}

// round 12
// speedup vs baseline: 1.6615x; 1.1198x over previous
#include <cuda_runtime.h>
#include <cuda_fp16.h>
#include <cstdint>

#define NGRAPH 2048
#define NPG 91
#define DIM 128
#define ORDER 3

// scratch
__device__ float    g_fvb[ORDER * NGRAPH * DIM];     // fv + bu (3 MB)
__device__ uint32_t g_wuth[ORDER * 128 * 68];        // Wu^T fp16, padded (stride 136 halves)

// ---------------- kernel 1: fvb (blocks 0..767) + prep Wu^T (blocks 768..770)
__global__ void __launch_bounds__(128) prep_kernel(const float* __restrict__ feats,
                                                   const float* __restrict__ Wu,
                                                   const float* __restrict__ Wv,
                                                   const float* __restrict__ bu,
                                                   const int* __restrict__ last_idx) {
    if (blockIdx.x >= 768) {
        int o = blockIdx.x - 768;
        const float* w = Wu + o * DIM * DIM;
        for (int i = threadIdx.x; i < 64 * 128; i += 128) {
            int d2 = i & 63, n = i >> 6;
            float a = w[(2 * d2) * DIM + n];
            float b = w[(2 * d2 + 1) * DIM + n];
            __half2 p = __floats2half2_rn(a, b);
            g_wuth[o * 128 * 68 + n * 68 + d2] = *(uint32_t*)&p;
        }
        return;
    }
    const int GPB = 8;
    int o  = blockIdx.x / (NGRAPH / GPB);
    int b0 = (blockIdx.x % (NGRAPH / GPB)) * GPB;
    int h  = threadIdx.x;
    __shared__ float xs[GPB][DIM];
    #pragma unroll
    for (int j = 0; j < GPB; j++) {
        int node = last_idx[o * NGRAPH + b0 + j];
        xs[j][h] = feats[node * DIM + h];
    }
    __syncthreads();
    float acc[GPB];
    float bv = bu[o * DIM + h];
    #pragma unroll
    for (int j = 0; j < GPB; j++) acc[j] = bv;
    const float* Wvo = Wv + o * DIM * DIM;
    #pragma unroll 8
    for (int d = 0; d < DIM; d++) {
        float w = Wvo[d * DIM + h];
        #pragma unroll
        for (int j = 0; j < GPB; j++) acc[j] += xs[j][d] * w;
    }
    #pragma unroll
    for (int j = 0; j < GPB; j++)
        g_fvb[(o * NGRAPH + b0 + j) * DIM + h] = acc[j];
}

// ---------------- fused main kernel (512 threads, 16 warps, 1 graph/CTA) ----
// A: 96 rows x 128 halves, stride 136 halves. WuT: double-buffered.
#define LDAH 136
#define OFF_A    0                        // 96*136*2 = 26112 B
#define OFF_WUT  26112                    // 2 x 34816 B -> end 95744
#define WUT_BUFB 34816
#define OFF_FV3  95744                    // 384 floats -> end 97280
#define OFF_WE3  97280                    // 384 floats -> end 98816
#define OFF_ER   98816                    // 8*96 floats = 3072 B -> end 101888
#define OFF_AL   101888                   // 96 floats -> end 102272
#define OFF_TP   102272                   // 384 floats (tail partials) -> 103808
#define SMEM_BYTES 103808                 // x2 CTAs = 207616 <= 227KB

__device__ __forceinline__ void ldsm_x4(uint32_t r[4], uint32_t saddr) {
    asm volatile("ldmatrix.sync.aligned.m8n8.x4.shared.b16 {%0,%1,%2,%3}, [%4];"
                 : "=r"(r[0]), "=r"(r[1]), "=r"(r[2]), "=r"(r[3])
                 : "r"(saddr));
}
__device__ __forceinline__ void mma_f16(float c[4], const uint32_t a[4],
                                        uint32_t b0, uint32_t b1) {
    asm volatile(
        "mma.sync.aligned.m16n8k16.row.col.f32.f16.f16.f32 "
        "{%0,%1,%2,%3}, {%4,%5,%6,%7}, {%8,%9}, {%0,%1,%2,%3};"
        : "+f"(c[0]), "+f"(c[1]), "+f"(c[2]), "+f"(c[3])
        : "r"(a[0]), "r"(a[1]), "r"(a[2]), "r"(a[3]), "r"(b0), "r"(b1));
}

__global__ void __launch_bounds__(512, 2) fused_kernel(const float* __restrict__ feats,
                                                       const float* __restrict__ We,
                                                       const float* __restrict__ fvb,
                                                       float* __restrict__ out) {
    extern __shared__ char smc[];
    uint2*  sA2   = (uint2*)(smc + OFF_A);
    float*  sFV3  = (float*)(smc + OFF_FV3);
    float*  sWe3  = (float*)(smc + OFF_WE3);
    float*  sER   = (float*)(smc + OFF_ER);
    float*  sAL   = (float*)(smc + OFF_AL);
    float*  sTP   = (float*)(smc + OFF_TP);
    const __half* sAh = (const __half*)(smc + OFF_A);

    const int tid   = threadIdx.x;
    const int graph = blockIdx.x;         // 1 graph per CTA
    const int lane  = tid & 31;
    const int wid   = tid >> 5;
    const int warpM = wid >> 3;           // 0..1 -> 48 rows
    const int warpN = wid & 7;            // 0..7 -> 16 cols
    const int gid   = lane >> 2;
    const int tig   = lane & 3;

    // stage feats as fp16: 91 rows + 5 zero pad rows
    {
        const float4* f4 = (const float4*)(feats + (size_t)graph * NPG * DIM);
        for (int i = tid; i < NPG * 32; i += 512) {
            int r = i >> 5, c = i & 31;
            float4 v = f4[i];
            __half2 p0 = __floats2half2_rn(v.x, v.y);
            __half2 p1 = __floats2half2_rn(v.z, v.w);
            sA2[r * 34 + c] = make_uint2(*(uint32_t*)&p0, *(uint32_t*)&p1);
        }
        if (tid < 5 * 32) {
            int r = NPG + (tid >> 5), c = tid & 31;
            sA2[r * 34 + c] = make_uint2(0u, 0u);
        }
        // all orders' fv and We upfront
        if (tid < 384) {
            int o = tid >> 7, h = tid & 127;
            sFV3[tid] = fvb[(o * NGRAPH + graph) * DIM + h];
            sWe3[tid] = We[tid];
        }
        // WuT[0] into buffer 0
        const float4* src = (const float4*)g_wuth;
        float4* dst = (float4*)(smc + OFF_WUT);
        for (int i = tid; i < 2176; i += 512) dst[i] = src[i];
    }

    // ldmatrix base addresses
    uint32_t aBase[3];
    #pragma unroll
    for (int mt = 0; mt < 3; mt++) {
        const __half* p = sAh + (warpM * 48 + mt * 16 + (lane & 15)) * LDAH
                        + ((lane >> 4) << 3);
        aBase[mt] = (uint32_t)__cvta_generic_to_shared(p);
    }
    uint32_t bBase;
    {
        const __half* p = (const __half*)(smc + OFF_WUT)
            + (warpN * 16 + ((lane >> 4) << 3) + (lane & 7)) * LDAH
            + (((lane >> 3) & 1) << 3);
        bBase = (uint32_t)__cvta_generic_to_shared(p);
    }
    __syncthreads();

    for (int o = 0; o < ORDER; o++) {
        const uint32_t bufOff = (uint32_t)((o & 1) * WUT_BUFB);
        float acc[3][2][4];
        #pragma unroll
        for (int mt = 0; mt < 3; mt++)
            #pragma unroll
            for (int nt = 0; nt < 2; nt++) {
                acc[mt][nt][0] = 0.f; acc[mt][nt][1] = 0.f;
                acc[mt][nt][2] = 0.f; acc[mt][nt][3] = 0.f;
            }

        #pragma unroll
        for (int ks = 0; ks < 8; ks++) {
            const uint32_t kb = (uint32_t)(ks * 32);
            uint32_t afr[3][4];
            #pragma unroll
            for (int mt = 0; mt < 3; mt++) ldsm_x4(afr[mt], aBase[mt] + kb);
            uint32_t bfr[4];
            ldsm_x4(bfr, bBase + bufOff + kb);
            #pragma unroll
            for (int mt = 0; mt < 3; mt++) {
                mma_f16(acc[mt][0], afr[mt], bfr[0], bfr[1]);
                mma_f16(acc[mt][1], afr[mt], bfr[2], bfr[3]);
            }
        }

        // epilogue: e-row partials
        const float* sFV = sFV3 + o * DIM;
        const float* sWe = sWe3 + o * DIM;
        float ep[3][2];
        #pragma unroll
        for (int mt = 0; mt < 3; mt++) { ep[mt][0] = 0.f; ep[mt][1] = 0.f; }
        #pragma unroll
        for (int mt = 0; mt < 3; mt++) {
            int m0 = warpM * 48 + mt * 16 + gid;
            int m1 = m0 + 8;
            #pragma unroll
            for (int nt = 0; nt < 2; nt++) {
                int h = warpN * 16 + nt * 8 + tig * 2;
                float we0 = sWe[h], we1 = sWe[h + 1];
                if (m0 < NPG) {
                    float x0 = 0.5f * (acc[mt][nt][0] + sFV[h]);
                    float x1 = 0.5f * (acc[mt][nt][1] + sFV[h + 1]);
                    float t0, t1;
                    asm("tanh.approx.f32 %0, %1;" : "=f"(t0) : "f"(x0));
                    asm("tanh.approx.f32 %0, %1;" : "=f"(t1) : "f"(x1));
                    ep[mt][0] += we0 * (0.5f * t0 + 0.5f) + we1 * (0.5f * t1 + 0.5f);
                }
                if (m1 < NPG) {
                    float x2 = 0.5f * (acc[mt][nt][2] + sFV[h]);
                    float x3 = 0.5f * (acc[mt][nt][3] + sFV[h + 1]);
                    float t2, t3;
                    asm("tanh.approx.f32 %0, %1;" : "=f"(t2) : "f"(x2));
                    asm("tanh.approx.f32 %0, %1;" : "=f"(t3) : "f"(x3));
                    ep[mt][1] += we0 * (0.5f * t2 + 0.5f) + we1 * (0.5f * t3 + 0.5f);
                }
            }
        }
        #pragma unroll
        for (int mt = 0; mt < 3; mt++)
            #pragma unroll
            for (int q = 0; q < 2; q++) {
                float v = ep[mt][q];
                v += __shfl_xor_sync(0xffffffffu, v, 1);
                v += __shfl_xor_sync(0xffffffffu, v, 2);
                int m = warpM * 48 + mt * 16 + gid + q * 8;
                if (tig == 0 && m < NPG) sER[warpN * 96 + m] = v;
            }

        // stage next order's WuT into the other buffer (off critical path)
        if (o < ORDER - 1) {
            const float4* src = (const float4*)(g_wuth + (o + 1) * 128 * 68);
            float4* dst = (float4*)(smc + OFF_WUT + ((o + 1) & 1) * WUT_BUFB);
            for (int i = tid; i < 2176; i += 512) dst[i] = src[i];
        }
        __syncthreads();   // B1: sER complete

        // softmax over 91 nodes (warp 0)
        if (wid == 0) {
            float ev[3];
            #pragma unroll
            for (int j = 0; j < 3; j++) {
                int r = lane + 32 * j;
                if (r < NPG) {
                    float s = 0.f;
                    #pragma unroll
                    for (int bk = 0; bk < 8; bk++) s += sER[bk * 96 + r];
                    ev[j] = s;
                } else ev[j] = -1e30f;
            }
            float mx = fmaxf(ev[0], fmaxf(ev[1], ev[2]));
            #pragma unroll
            for (int s = 16; s; s >>= 1)
                mx = fmaxf(mx, __shfl_xor_sync(0xffffffffu, mx, s));
            float sum = 0.f;
            #pragma unroll
            for (int j = 0; j < 3; j++) {
                ev[j] = (lane + 32 * j < NPG) ? __expf(ev[j] - mx) : 0.f;
                sum += ev[j];
            }
            #pragma unroll
            for (int s = 16; s; s >>= 1)
                sum += __shfl_xor_sync(0xffffffffu, sum, s);
            float inv = 1.f / sum;
            #pragma unroll
            for (int j = 0; j < 3; j++) {
                int r = lane + 32 * j;
                if (r < NPG) sAL[r] = ev[j] * inv;
            }
        }
        __syncthreads();   // B2: sAL ready

        // rst[graph,o,:] = sum_m alpha[m] * feats_h[m,:]  (4 row-parts)
        {
            int part = tid >> 7;          // 0..3
            int h    = tid & 127;
            int r0i  = part * 23;
            int cnt  = (part == 3) ? 22 : 23;
            const __half* aB  = sAh + r0i * LDAH + h;
            const float*  alB = sAL + r0i;
            float r0 = 0.f;
            #pragma unroll 23
            for (int r = 0; r < cnt; r++)
                r0 += alB[r] * __half2float(aB[r * LDAH]);
            if (part) sTP[(part - 1) * 128 + h] = r0;
            __syncthreads();   // B3: partials ready
            if (!part)
                out[(graph * ORDER + o) * DIM + h] =
                    r0 + sTP[h] + sTP[128 + h] + sTP[256 + h];
        }
    }
}

extern "C" void kernel_launch(void* const* d_in, const int* in_sizes, int n_in,
                              void* d_out, int out_size) {
    const float* feats    = (const float*)d_in[0];
    const float* Wu       = (const float*)d_in[1];
    const float* bu       = (const float*)d_in[2];
    const float* Wv       = (const float*)d_in[3];
    const float* We       = (const float*)d_in[4];
    const int*   last_idx = (const int*)d_in[6];
    float* out = (float*)d_out;

    prep_kernel<<<768 + ORDER, 128>>>(feats, Wu, Wv, bu, last_idx);

    const float* fvb_ptr;
    cudaGetSymbolAddress((void**)&fvb_ptr, g_fvb);

    cudaFuncSetAttribute(fused_kernel, cudaFuncAttributeMaxDynamicSharedMemorySize,
                         SMEM_BYTES);
    fused_kernel<<<NGRAPH, 512, SMEM_BYTES>>>(feats, We, fvb_ptr, out);
}